// round 13
// baseline (speedup 1.0000x reference)
#include <cuda_runtime.h>
#include <cuda_bf16.h>
#include <cuda_fp16.h>
#include <math.h>
#include <stdint.h>

// ---------------- problem constants ----------------
#define NB 4
#define HH 48
#define WW 48
#define CC 1024
#define COUT 512
#define GG 4
#define GC 256
#define PIX 9216            // NB*HH*WW
#define NFUSE 128           // offset(72) + mask(36) = 108, padded to 128

// ---------------- scratch (no cudaMalloc allowed) ----------------
__device__ __half g_xh[PIX * CC];               // in_proj output (fp16, gathered by dcn)
__device__ float g_om[PIX * NFUSE];             // fused offset+mask logits
__device__ __nv_bfloat16 g_in_hi[PIX * CC];
__device__ __nv_bfloat16 g_in_lo[PIX * CC];
__device__ __nv_bfloat16 g_x1_hi[PIX * CC];
__device__ __nv_bfloat16 g_x1_lo[PIX * CC];
__device__ __nv_bfloat16 g_dcn_hi[PIX * CC];
__device__ __nv_bfloat16 g_dcn_lo[PIX * CC];
__device__ __nv_bfloat16 g_win_hi[CC * CC];
__device__ __nv_bfloat16 g_win_lo[CC * CC];
__device__ __nv_bfloat16 g_wout_hi[COUT * CC];
__device__ __nv_bfloat16 g_wout_lo[COUT * CC];
__device__ __nv_bfloat16 g_wom_hi[NFUSE * CC];
__device__ __nv_bfloat16 g_wom_lo[NFUSE * CC];
__device__ float g_bom[NFUSE];
__device__ float g_wdwt[9 * CC];                // transposed depthwise weights [tap][C]

// ---------------- helpers ----------------
__device__ __forceinline__ uint32_t smem_to_u32(const void* p) {
    uint32_t a;
    asm("{ .reg .u64 t; cvta.to.shared.u64 t, %1; cvt.u32.u64 %0, t; }" : "=r"(a) : "l"(p));
    return a;
}
__device__ __forceinline__ void cpa16(uint32_t s, const void* g) {
    asm volatile("cp.async.cg.shared.global [%0], [%1], 16;" :: "r"(s), "l"(g));
}
#define CP_COMMIT() asm volatile("cp.async.commit_group;" ::: "memory")
#define CP_WAIT1()  asm volatile("cp.async.wait_group 1;" ::: "memory")
#define CP_WAIT0()  asm volatile("cp.async.wait_group 0;" ::: "memory")
#define LDSM4(r0, r1, r2, r3, addr) \
    asm volatile("ldmatrix.sync.aligned.m8n8.x4.shared.b16 {%0,%1,%2,%3}, [%4];" \
                 : "=r"(r0), "=r"(r1), "=r"(r2), "=r"(r3) : "r"(addr))

// mma.sync m16n8k16 bf16 -> f32 (base ISA, works on sm_100)
__device__ __forceinline__ void mma16816(float* d, const uint32_t* a, uint32_t b0, uint32_t b1) {
    asm volatile(
        "mma.sync.aligned.m16n8k16.row.col.f32.bf16.bf16.f32 "
        "{%0,%1,%2,%3}, {%4,%5,%6,%7}, {%8,%9}, {%0,%1,%2,%3};"
        : "+f"(d[0]), "+f"(d[1]), "+f"(d[2]), "+f"(d[3])
        : "r"(a[0]), "r"(a[1]), "r"(a[2]), "r"(a[3]), "r"(b0), "r"(b1));
}

__device__ __forceinline__ void split1(float v, __nv_bfloat16& h, __nv_bfloat16& l) {
    h = __float2bfloat16(v);
    l = __float2bfloat16(v - __bfloat162float(h));
}

// ================= HMMA GEMM: C[M,N] = A @ B^T + bias (templated output) =================
// 128m x 64n CTA tile, 256 threads = 8 warps (32m x 32n each), K chunk 64.
// 2-stage cp.async pipeline, ldmatrix, XOR swizzle. 96KB smem -> 2 CTAs/SM.
#define KC 64
#define A_TILE_B 16384
#define B_TILE_B 8192
#define STAGE_B (2 * A_TILE_B + 2 * B_TILE_B)   // 48KB
#define GEMM_SMEM (2 * STAGE_B)                 // 96KB

template <typename OutT>
__global__ __launch_bounds__(256, 2)
void gemm_mma(const __nv_bfloat16* __restrict__ Ah, const __nv_bfloat16* __restrict__ Al,
              const __nv_bfloat16* __restrict__ Bh, const __nv_bfloat16* __restrict__ Bl,
              const float* __restrict__ bias, OutT* __restrict__ C, int N, int K) {
    extern __shared__ char smem[];
    const uint32_t sb = smem_to_u32(smem);

    const int t = threadIdx.x;
    const int lane = t & 31, w = t >> 5;
    const int wm = w >> 1;
    const int wn = w & 1;
    const int gid = lane >> 2;
    const int tig = lane & 3;

    const int bm = blockIdx.y * 128;
    const int bn = blockIdx.x * 64;

    uint32_t ldA_dst[4], ldA_src[4], ldB_dst[2], ldB_src[2];
#pragma unroll
    for (int i = 0; i < 4; i++) {
        int idx = t + i * 256;
        int row = idx >> 3, q = idx & 7;
        uint32_t off = (uint32_t)(row * 128 + q * 16);
        ldA_dst[i] = off ^ ((uint32_t)(row & 7) << 4);
        ldA_src[i] = (uint32_t)row * (uint32_t)K * 2u + (uint32_t)q * 16u;
    }
#pragma unroll
    for (int i = 0; i < 2; i++) {
        int idx = t + i * 256;
        int row = idx >> 3, q = idx & 7;
        uint32_t off = (uint32_t)(row * 128 + q * 16);
        ldB_dst[i] = off ^ ((uint32_t)(row & 7) << 4);
        ldB_src[i] = (uint32_t)row * (uint32_t)K * 2u + (uint32_t)q * 16u;
    }
    const char* gAh = (const char*)(Ah + (size_t)bm * K);
    const char* gAl = (const char*)(Al + (size_t)bm * K);
    const char* gBh = (const char*)(Bh + (size_t)bn * K);
    const char* gBl = (const char*)(Bl + (size_t)bn * K);

    const int rA = lane & 7, tA = lane >> 3;
    const uint32_t rowA = (uint32_t)(wm * 32 + (tA & 1) * 8 + rA) * 128;
    const uint32_t kselA = (uint32_t)(tA >> 1) * 16;
    const uint32_t swA = (uint32_t)rA << 4;
    uint32_t rowB[2];
#pragma unroll
    for (int np = 0; np < 2; np++)
        rowB[np] = (uint32_t)(wn * 32 + np * 16 + ((lane >> 4) & 1) * 8 + (lane & 7)) * 128;
    const uint32_t kselB = (uint32_t)((lane >> 3) & 1) * 16;
    const uint32_t swB = (uint32_t)(lane & 7) << 4;

    float acc[2][4][4];
#pragma unroll
    for (int i = 0; i < 2; i++)
#pragma unroll
        for (int j = 0; j < 4; j++)
#pragma unroll
            for (int q = 0; q < 4; q++) acc[i][j][q] = 0.f;

    const int NCH = K / KC;

    auto load_stage = [&](uint32_t stg, uint32_t coff) {
        const uint32_t sAh = stg, sAl = stg + A_TILE_B;
        const uint32_t sBh = stg + 2 * A_TILE_B, sBl = stg + 2 * A_TILE_B + B_TILE_B;
#pragma unroll
        for (int i = 0; i < 4; i++) {
            cpa16(sAh + ldA_dst[i], gAh + coff + ldA_src[i]);
            cpa16(sAl + ldA_dst[i], gAl + coff + ldA_src[i]);
        }
#pragma unroll
        for (int i = 0; i < 2; i++) {
            cpa16(sBh + ldB_dst[i], gBh + coff + ldB_src[i]);
            cpa16(sBl + ldB_dst[i], gBl + coff + ldB_src[i]);
        }
    };

    load_stage(sb, 0);
    CP_COMMIT();

    for (int c = 0; c < NCH; c++) {
        const int s = c & 1;
        if (c + 1 < NCH) {
            load_stage(sb + (uint32_t)(s ^ 1) * STAGE_B, (uint32_t)(c + 1) * KC * 2u);
            CP_COMMIT();
            CP_WAIT1();
        } else {
            CP_WAIT0();
        }
        __syncthreads();

        const uint32_t stg = sb + (uint32_t)s * STAGE_B;
        const uint32_t sAh = stg, sAl = stg + A_TILE_B;
        const uint32_t sBh = stg + 2 * A_TILE_B, sBl = stg + 2 * A_TILE_B + B_TILE_B;

#pragma unroll
        for (int ks = 0; ks < 4; ks++) {
            const uint32_t kA = ((uint32_t)(ks * 32) + kselA) ^ swA;
            const uint32_t kB = ((uint32_t)(ks * 32) + kselB) ^ swB;

            uint32_t aH[2][4], aL[2][4];
            LDSM4(aH[0][0], aH[0][1], aH[0][2], aH[0][3], sAh + rowA + kA);
            LDSM4(aH[1][0], aH[1][1], aH[1][2], aH[1][3], sAh + rowA + 2048 + kA);
            LDSM4(aL[0][0], aL[0][1], aL[0][2], aL[0][3], sAl + rowA + kA);
            LDSM4(aL[1][0], aL[1][1], aL[1][2], aL[1][3], sAl + rowA + 2048 + kA);

#pragma unroll
            for (int np = 0; np < 2; np++) {
                uint32_t bh[4], bl[4];
                LDSM4(bh[0], bh[1], bh[2], bh[3], sBh + rowB[np] + kB);
                LDSM4(bl[0], bl[1], bl[2], bl[3], sBl + rowB[np] + kB);
#pragma unroll
                for (int half = 0; half < 2; half++) {
                    const int ns = np * 2 + half;
                    const uint32_t bh0 = bh[half * 2], bh1 = bh[half * 2 + 1];
                    const uint32_t bl0 = bl[half * 2], bl1 = bl[half * 2 + 1];
#pragma unroll
                    for (int ms = 0; ms < 2; ms++) {
                        mma16816(acc[ms][ns], aH[ms], bh0, bh1);
                        mma16816(acc[ms][ns], aH[ms], bl0, bl1);
                        mma16816(acc[ms][ns], aL[ms], bh0, bh1);
                    }
                }
            }
        }
        __syncthreads();
    }

    // epilogue (fp32 or fp16 output)
#pragma unroll
    for (int ms = 0; ms < 2; ms++) {
        int row = bm + wm * 32 + ms * 16 + gid;
#pragma unroll
        for (int ns = 0; ns < 4; ns++) {
            int col = bn + wn * 32 + ns * 8 + tig * 2;
            float bx = __ldg(bias + col), by = __ldg(bias + col + 1);
            float2 v0 = make_float2(acc[ms][ns][0] + bx, acc[ms][ns][1] + by);
            float2 v1 = make_float2(acc[ms][ns][2] + bx, acc[ms][ns][3] + by);
            if constexpr (sizeof(OutT) == 4) {
                *reinterpret_cast<float2*>((float*)C + (size_t)row * N + col) = v0;
                *reinterpret_cast<float2*>((float*)C + (size_t)(row + 8) * N + col) = v1;
            } else {
                *reinterpret_cast<__half2*>((__half*)C + (size_t)row * N + col) =
                    __float22half2_rn(v0);
                *reinterpret_cast<__half2*>((__half*)C + (size_t)(row + 8) * N + col) =
                    __float22half2_rn(v1);
            }
        }
    }
}

// ================= fused conversion kernel (one launch) =================
#define CONV_BLOCKS 11300

__global__ __launch_bounds__(256)
void conv_all_kernel(const float* __restrict__ input, const float* __restrict__ win,
                     const float* __restrict__ wout,
                     const float* __restrict__ woff, const float* __restrict__ boff,
                     const float* __restrict__ wmask, const float* __restrict__ bmask,
                     const float* __restrict__ wdw) {
    const int b = blockIdx.x;
    const int t = threadIdx.x;
    if (b < 10752) {
        const float* src; __nv_bfloat16 *hi, *lo; int i;
        if (b < 9216)       { src = input; hi = g_in_hi;  lo = g_in_lo;  i = b * 256 + t; }
        else if (b < 10240) { src = win;   hi = g_win_hi; lo = g_win_lo; i = (b - 9216) * 256 + t; }
        else                { src = wout;  hi = g_wout_hi; lo = g_wout_lo; i = (b - 10240) * 256 + t; }
        float4 v = reinterpret_cast<const float4*>(src)[i];
        __nv_bfloat16 h0, h1, h2, h3, l0, l1, l2, l3;
        split1(v.x, h0, l0); split1(v.y, h1, l1); split1(v.z, h2, l2); split1(v.w, h3, l3);
        __nv_bfloat162* hp = reinterpret_cast<__nv_bfloat162*>(hi) + i * 2;
        __nv_bfloat162* lp = reinterpret_cast<__nv_bfloat162*>(lo) + i * 2;
        hp[0] = __nv_bfloat162(h0, h1); hp[1] = __nv_bfloat162(h2, h3);
        lp[0] = __nv_bfloat162(l0, l1); lp[1] = __nv_bfloat162(l2, l3);
    } else if (b < 11264) {
        int i = (b - 10752) * 256 + t;
        int r = i >> 10, c = i & 1023;
        float v = 0.f;
        if (r < 72) v = woff[r * CC + c];
        else if (r < 108) v = wmask[(r - 72) * CC + c];
        __nv_bfloat16 h, l; split1(v, h, l);
        g_wom_hi[i] = h; g_wom_lo[i] = l;
        if (i < NFUSE) {
            float bb = 0.f;
            if (i < 72) bb = boff[i];
            else if (i < 108) bb = bmask[i - 72];
            g_bom[i] = bb;
        }
    } else {
        int i = (b - 11264) * 256 + t;
        int k = i >> 10, c = i & 1023;
        g_wdwt[k * CC + c] = wdw[c * 9 + k];
    }
}

// ================= depthwise conv 3x3 + LN + GELU -> split bf16 =================
__global__ __launch_bounds__(256)
void dw_ln_gelu_kernel(const float* __restrict__ in,
                       const float* __restrict__ bdw, const float* __restrict__ gamma,
                       const float* __restrict__ beta,
                       __nv_bfloat16* __restrict__ x1h, __nv_bfloat16* __restrict__ x1l) {
    const int pix = blockIdx.x;
    const int n = pix / (HH * WW);
    const int hw = pix % (HH * WW);
    const int h = hw / WW;
    const int w = hw % WW;
    const int t = threadIdx.x;
    const int c4 = t * 4;

    float4 acc = make_float4(0.f, 0.f, 0.f, 0.f);
#pragma unroll
    for (int kh = 0; kh < 3; kh++) {
        int y = h + kh - 1;
        if ((unsigned)y >= HH) continue;
#pragma unroll
        for (int kw = 0; kw < 3; kw++) {
            int x = w + kw - 1;
            if ((unsigned)x >= WW) continue;
            const float4 pv = *reinterpret_cast<const float4*>(
                in + (((size_t)n * HH + y) * WW + x) * CC + c4);
            const float4 wv = *reinterpret_cast<const float4*>(
                g_wdwt + (kh * 3 + kw) * CC + c4);
            acc.x = fmaf(pv.x, wv.x, acc.x);
            acc.y = fmaf(pv.y, wv.y, acc.y);
            acc.z = fmaf(pv.z, wv.z, acc.z);
            acc.w = fmaf(pv.w, wv.w, acc.w);
        }
    }
    const float4 bv = *reinterpret_cast<const float4*>(bdw + c4);
    float vals[4] = {acc.x + bv.x, acc.y + bv.y, acc.z + bv.z, acc.w + bv.w};
    float s = 0.f, s2 = 0.f;
#pragma unroll
    for (int i = 0; i < 4; i++) { s += vals[i]; s2 = fmaf(vals[i], vals[i], s2); }

    __shared__ float sh[16];
#pragma unroll
    for (int o = 16; o > 0; o >>= 1) {
        s  += __shfl_down_sync(0xFFFFFFFFu, s, o);
        s2 += __shfl_down_sync(0xFFFFFFFFu, s2, o);
    }
    int wd = t >> 5, ln = t & 31;
    if (ln == 0) { sh[wd] = s; sh[8 + wd] = s2; }
    __syncthreads();
    if (t == 0) {
        float S = 0.f, S2 = 0.f;
#pragma unroll
        for (int i = 0; i < 8; i++) { S += sh[i]; S2 += sh[8 + i]; }
        sh[0] = S; sh[8] = S2;
    }
    __syncthreads();
    float mean = sh[0] * (1.f / 1024.f);
    float var  = sh[8] * (1.f / 1024.f) - mean * mean;
    float rstd = rsqrtf(var + 1e-6f);

    const float4 gv = *reinterpret_cast<const float4*>(gamma + c4);
    const float4 btv = *reinterpret_cast<const float4*>(beta + c4);
    const float ga[4] = {gv.x, gv.y, gv.z, gv.w};
    const float be[4] = {btv.x, btv.y, btv.z, btv.w};

    __nv_bfloat16 hh[4], ll[4];
#pragma unroll
    for (int i = 0; i < 4; i++) {
        float y = (vals[i] - mean) * rstd * ga[i] + be[i];
        float g = 0.5f * y * (1.f + erff(y * 0.70710678118654752f));
        split1(g, hh[i], ll[i]);
    }
    const size_t ob = (size_t)pix * CC + c4;
    __nv_bfloat162* hp = reinterpret_cast<__nv_bfloat162*>(x1h + ob);
    __nv_bfloat162* lp = reinterpret_cast<__nv_bfloat162*>(x1l + ob);
    hp[0] = __nv_bfloat162(hh[0], hh[1]); hp[1] = __nv_bfloat162(hh[2], hh[3]);
    lp[0] = __nv_bfloat162(ll[0], ll[1]); lp[1] = __nv_bfloat162(ll[2], ll[3]);
}

// ================= DCNv3 core -> split bf16 (branchless gather, fp16 x) =================
__device__ __forceinline__ float4 ld_half4(const __half* p) {
    float2 raw = *reinterpret_cast<const float2*>(p);
    __half2 a = *reinterpret_cast<__half2*>(&raw.x);
    __half2 b = *reinterpret_cast<__half2*>(&raw.y);
    float2 f01 = __half22float2(a), f23 = __half22float2(b);
    return make_float4(f01.x, f01.y, f23.x, f23.y);
}

__global__ __launch_bounds__(256)
void dcn_kernel(const __half* __restrict__ x, const float* __restrict__ om,
                __nv_bfloat16* __restrict__ oh, __nv_bfloat16* __restrict__ ol) {
    const int pix = blockIdx.x;
    const int n = pix / (HH * WW);
    const int hw = pix % (HH * WW);
    const int h = hw / WW;
    const int w = hw % WW;
    const int t = threadIdx.x;
    const int g = t >> 6;
    const int ci = (t & 63) << 2;

    const float* row = om + (size_t)pix * NFUSE;
    const float* mrow = row + 72 + g * 9;
    const float* orow = row + g * 18;

    float ml[9], mx = -1e30f;
#pragma unroll
    for (int p = 0; p < 9; p++) { ml[p] = mrow[p]; mx = fmaxf(mx, ml[p]); }
    float se = 0.f;
#pragma unroll
    for (int p = 0; p < 9; p++) { ml[p] = expf(ml[p] - mx); se += ml[p]; }
    float inv = 1.f / se;

    const __half* xg = x + g * GC + ci;
    const size_t nrow = (size_t)n * HH;
    float a0 = 0.f, a1 = 0.f, a2 = 0.f, a3 = 0.f;

#pragma unroll
    for (int p = 0; p < 9; p++) {
        float ox = orow[2 * p + 0];
        float oy = orow[2 * p + 1];
        float ux = (float)(w + (p / 3) - 1) + ox;
        float uy = (float)(h + (p % 3) - 1) + oy;
        float x0f = floorf(ux), y0f = floorf(uy);
        float fx = ux - x0f, fy = uy - y0f;
        int x0 = (int)x0f, y0 = (int)y0f;
        int x1i = x0 + 1, y1i = y0 + 1;

        float mx0 = ((unsigned)x0 < WW) ? 1.f : 0.f;
        float mx1 = ((unsigned)x1i < WW) ? 1.f : 0.f;
        float my0 = ((unsigned)y0 < HH) ? 1.f : 0.f;
        float my1 = ((unsigned)y1i < HH) ? 1.f : 0.f;
        int x0c = min(max(x0, 0), WW - 1), x1c = min(max(x1i, 0), WW - 1);
        int y0c = min(max(y0, 0), HH - 1), y1c = min(max(y1i, 0), HH - 1);

        const __half* r0 = xg + ((nrow + y0c) * WW) * CC;
        const __half* r1 = xg + ((nrow + y1c) * WW) * CC;
        float4 v00 = ld_half4(r0 + (size_t)x0c * CC);
        float4 v01 = ld_half4(r0 + (size_t)x1c * CC);
        float4 v10 = ld_half4(r1 + (size_t)x0c * CC);
        float4 v11 = ld_half4(r1 + (size_t)x1c * CC);

        const float wt = ml[p] * inv;
        const float w00 = (1.f - fx) * (1.f - fy) * my0 * mx0 * wt;
        const float w01 = fx * (1.f - fy) * my0 * mx1 * wt;
        const float w10 = (1.f - fx) * fy * my1 * mx0 * wt;
        const float w11 = fx * fy * my1 * mx1 * wt;

        a0 = fmaf(w00, v00.x, fmaf(w01, v01.x, fmaf(w10, v10.x, fmaf(w11, v11.x, a0))));
        a1 = fmaf(w00, v00.y, fmaf(w01, v01.y, fmaf(w10, v10.y, fmaf(w11, v11.y, a1))));
        a2 = fmaf(w00, v00.z, fmaf(w01, v01.z, fmaf(w10, v10.z, fmaf(w11, v11.z, a2))));
        a3 = fmaf(w00, v00.w, fmaf(w01, v01.w, fmaf(w10, v10.w, fmaf(w11, v11.w, a3))));
    }
    __nv_bfloat16 h0, h1, h2, h3, l0, l1, l2, l3;
    split1(a0, h0, l0); split1(a1, h1, l1); split1(a2, h2, l2); split1(a3, h3, l3);
    const size_t o = (size_t)pix * CC + g * GC + ci;
    __nv_bfloat162* hp = reinterpret_cast<__nv_bfloat162*>(oh + o);
    __nv_bfloat162* lp = reinterpret_cast<__nv_bfloat162*>(ol + o);
    hp[0] = __nv_bfloat162(h0, h1); hp[1] = __nv_bfloat162(h2, h3);
    lp[0] = __nv_bfloat162(l0, l1); lp[1] = __nv_bfloat162(l2, l3);
}

// ================= launch (capture-forked dual stream) =================
extern "C" void kernel_launch(void* const* d_in, const int* in_sizes, int n_in,
                              void* d_out, int out_size) {
    const float* input     = (const float*)d_in[0];
    const float* w_in_proj = (const float*)d_in[1];
    const float* b_in_proj = (const float*)d_in[2];
    const float* w_dw      = (const float*)d_in[3];
    const float* b_dw      = (const float*)d_in[4];
    const float* ln_gamma  = (const float*)d_in[5];
    const float* ln_beta   = (const float*)d_in[6];
    const float* w_offset  = (const float*)d_in[7];
    const float* b_offset  = (const float*)d_in[8];
    const float* w_mask    = (const float*)d_in[9];
    const float* b_mask    = (const float*)d_in[10];
    const float* w_out     = (const float*)d_in[11];
    const float* b_out     = (const float*)d_in[12];
    float* out = (float*)d_out;

    float *om, *bom;
    __half* xh;
    __nv_bfloat16 *inh, *inl, *x1h, *x1l, *dch, *dcl;
    __nv_bfloat16 *winh, *winl, *wouth, *woutl, *womh, *woml;
    cudaGetSymbolAddress((void**)&xh,   g_xh);
    cudaGetSymbolAddress((void**)&om,   g_om);
    cudaGetSymbolAddress((void**)&bom,  g_bom);
    cudaGetSymbolAddress((void**)&inh,  g_in_hi);
    cudaGetSymbolAddress((void**)&inl,  g_in_lo);
    cudaGetSymbolAddress((void**)&x1h,  g_x1_hi);
    cudaGetSymbolAddress((void**)&x1l,  g_x1_lo);
    cudaGetSymbolAddress((void**)&dch,  g_dcn_hi);
    cudaGetSymbolAddress((void**)&dcl,  g_dcn_lo);
    cudaGetSymbolAddress((void**)&winh, g_win_hi);
    cudaGetSymbolAddress((void**)&winl, g_win_lo);
    cudaGetSymbolAddress((void**)&wouth, g_wout_hi);
    cudaGetSymbolAddress((void**)&woutl, g_wout_lo);
    cudaGetSymbolAddress((void**)&womh, g_wom_hi);
    cudaGetSymbolAddress((void**)&woml, g_wom_lo);

    cudaFuncSetAttribute(gemm_mma<float>, cudaFuncAttributeMaxDynamicSharedMemorySize,
                         GEMM_SMEM);
    cudaFuncSetAttribute(gemm_mma<__half>, cudaFuncAttributeMaxDynamicSharedMemorySize,
                         GEMM_SMEM);

    cudaStream_t s1;
    cudaStreamCreateWithFlags(&s1, cudaStreamNonBlocking);
    cudaEvent_t eFork, eJoin;
    cudaEventCreateWithFlags(&eFork, cudaEventDisableTiming);
    cudaEventCreateWithFlags(&eJoin, cudaEventDisableTiming);

    // (1) all conversions in one launch (main stream)
    conv_all_kernel<<<CONV_BLOCKS, 256>>>(input, w_in_proj, w_out,
                                          w_offset, b_offset, w_mask, b_mask, w_dw);

    // fork: side chain does dw -> om gemm
    cudaEventRecord(eFork, 0);
    cudaStreamWaitEvent(s1, eFork, 0);

    // (2,3) side stream
    dw_ln_gelu_kernel<<<PIX, 256, 0, s1>>>(input, b_dw, ln_gamma, ln_beta, x1h, x1l);
    gemm_mma<float><<<dim3(NFUSE / 64, PIX / 128), 256, GEMM_SMEM, s1>>>(
        x1h, x1l, womh, woml, bom, om, NFUSE, CC);

    // (4) main stream: in_proj -> fp16 x
    gemm_mma<__half><<<dim3(CC / 64, PIX / 128), 256, GEMM_SMEM>>>(
        inh, inl, winh, winl, b_in_proj, xh, CC, CC);

    // join
    cudaEventRecord(eJoin, s1);
    cudaStreamWaitEvent(0, eJoin, 0);

    // (5) dcn (fp16 gather), (6) out projection (fp32 to d_out)
    dcn_kernel<<<PIX, 256>>>(xh, om, dch, dcl);
    gemm_mma<float><<<dim3(COUT / 64, PIX / 128), 256, GEMM_SMEM>>>(
        dch, dcl, wouth, woutl, b_out, out, COUT, CC);
}

// round 15
// speedup vs baseline: 1.0568x; 1.0568x over previous
#include <cuda_runtime.h>
#include <cuda_bf16.h>
#include <math.h>
#include <stdint.h>

// ---------------- problem constants ----------------
#define NB 4
#define HH 48
#define WW 48
#define CC 1024
#define COUT 512
#define GG 4
#define GC 256
#define PIX 9216            // NB*HH*WW
#define NFUSE 128           // offset(72) + mask(36) = 108, padded to 128

// ---------------- scratch (no cudaMalloc allowed) ----------------
__device__ float g_x[PIX * CC];                 // in_proj output (fp32, gathered by dcn)
__device__ float g_om[PIX * NFUSE];             // fused offset+mask logits
__device__ __nv_bfloat16 g_in_hi[PIX * CC];
__device__ __nv_bfloat16 g_in_lo[PIX * CC];
__device__ __nv_bfloat16 g_x1_hi[PIX * CC];
__device__ __nv_bfloat16 g_x1_lo[PIX * CC];
__device__ __nv_bfloat16 g_dcn_hi[PIX * CC];
__device__ __nv_bfloat16 g_dcn_lo[PIX * CC];
__device__ __nv_bfloat16 g_win_hi[CC * CC];
__device__ __nv_bfloat16 g_win_lo[CC * CC];
__device__ __nv_bfloat16 g_wout_hi[COUT * CC];
__device__ __nv_bfloat16 g_wout_lo[COUT * CC];
__device__ __nv_bfloat16 g_wom_hi[NFUSE * CC];
__device__ __nv_bfloat16 g_wom_lo[NFUSE * CC];
__device__ float g_bom[NFUSE];
__device__ float g_wdwt[9 * CC];                // transposed depthwise weights [tap][C]

// ---------------- helpers ----------------
__device__ __forceinline__ uint32_t smem_to_u32(const void* p) {
    uint32_t a;
    asm("{ .reg .u64 t; cvta.to.shared.u64 t, %1; cvt.u32.u64 %0, t; }" : "=r"(a) : "l"(p));
    return a;
}
__device__ __forceinline__ void cpa16(uint32_t s, const void* g) {
    asm volatile("cp.async.cg.shared.global [%0], [%1], 16;" :: "r"(s), "l"(g));
}
#define CP_COMMIT() asm volatile("cp.async.commit_group;" ::: "memory")
#define CP_WAIT0()  asm volatile("cp.async.wait_group 0;" ::: "memory")
#define LDSM4(r0, r1, r2, r3, addr) \
    asm volatile("ldmatrix.sync.aligned.m8n8.x4.shared.b16 {%0,%1,%2,%3}, [%4];" \
                 : "=r"(r0), "=r"(r1), "=r"(r2), "=r"(r3) : "r"(addr))

// mma.sync m16n8k16 bf16 -> f32 (base ISA, works on sm_100)
__device__ __forceinline__ void mma16816(float* d, const uint32_t* a, uint32_t b0, uint32_t b1) {
    asm volatile(
        "mma.sync.aligned.m16n8k16.row.col.f32.bf16.bf16.f32 "
        "{%0,%1,%2,%3}, {%4,%5,%6,%7}, {%8,%9}, {%0,%1,%2,%3};"
        : "+f"(d[0]), "+f"(d[1]), "+f"(d[2]), "+f"(d[3])
        : "r"(a[0]), "r"(a[1]), "r"(a[2]), "r"(a[3]), "r"(b0), "r"(b1));
}

__device__ __forceinline__ void split1(float v, __nv_bfloat16& h, __nv_bfloat16& l) {
    h = __float2bfloat16(v);
    l = __float2bfloat16(v - __bfloat162float(h));
}

// ================= HMMA GEMM: C[M,N] = A @ B^T + bias =================
// 128m x 64n CTA tile, 256 threads = 8 warps (32m x 32n), K chunk 64.
// 2-stage cp.async pipeline, intra-chunk software pipelining:
// compute ks0 -> issue next-chunk loads -> compute ks1..3 -> wait -> sync.
#define KC 64
#define A_TILE_B 16384
#define B_TILE_B 8192
#define STAGE_B (2 * A_TILE_B + 2 * B_TILE_B)   // 48KB
#define GEMM_SMEM (2 * STAGE_B)                 // 96KB -> 2 CTAs/SM

__global__ __launch_bounds__(256, 2)
void gemm_mma(const __nv_bfloat16* __restrict__ Ah, const __nv_bfloat16* __restrict__ Al,
              const __nv_bfloat16* __restrict__ Bh, const __nv_bfloat16* __restrict__ Bl,
              const float* __restrict__ bias, float* __restrict__ C, int N, int K) {
    extern __shared__ char smem[];
    const uint32_t sb = smem_to_u32(smem);

    const int t = threadIdx.x;
    const int lane = t & 31, w = t >> 5;
    const int wm = w >> 1;
    const int wn = w & 1;
    const int gid = lane >> 2;
    const int tig = lane & 3;

    const int bm = blockIdx.y * 128;
    const int bn = blockIdx.x * 64;

    uint32_t ldA_dst[4], ldA_src[4], ldB_dst[2], ldB_src[2];
#pragma unroll
    for (int i = 0; i < 4; i++) {
        int idx = t + i * 256;
        int row = idx >> 3, q = idx & 7;
        uint32_t off = (uint32_t)(row * 128 + q * 16);
        ldA_dst[i] = off ^ ((uint32_t)(row & 7) << 4);
        ldA_src[i] = (uint32_t)row * (uint32_t)K * 2u + (uint32_t)q * 16u;
    }
#pragma unroll
    for (int i = 0; i < 2; i++) {
        int idx = t + i * 256;
        int row = idx >> 3, q = idx & 7;
        uint32_t off = (uint32_t)(row * 128 + q * 16);
        ldB_dst[i] = off ^ ((uint32_t)(row & 7) << 4);
        ldB_src[i] = (uint32_t)row * (uint32_t)K * 2u + (uint32_t)q * 16u;
    }
    const char* gAh = (const char*)(Ah + (size_t)bm * K);
    const char* gAl = (const char*)(Al + (size_t)bm * K);
    const char* gBh = (const char*)(Bh + (size_t)bn * K);
    const char* gBl = (const char*)(Bl + (size_t)bn * K);

    const int rA = lane & 7, tA = lane >> 3;
    const uint32_t rowA = (uint32_t)(wm * 32 + (tA & 1) * 8 + rA) * 128;
    const uint32_t kselA = (uint32_t)(tA >> 1) * 16;
    const uint32_t swA = (uint32_t)rA << 4;
    uint32_t rowB[2];
#pragma unroll
    for (int np = 0; np < 2; np++)
        rowB[np] = (uint32_t)(wn * 32 + np * 16 + ((lane >> 4) & 1) * 8 + (lane & 7)) * 128;
    const uint32_t kselB = (uint32_t)((lane >> 3) & 1) * 16;
    const uint32_t swB = (uint32_t)(lane & 7) << 4;

    float acc[2][4][4];
#pragma unroll
    for (int i = 0; i < 2; i++)
#pragma unroll
        for (int j = 0; j < 4; j++)
#pragma unroll
            for (int q = 0; q < 4; q++) acc[i][j][q] = 0.f;

    const int NCH = K / KC;

    auto load_stage = [&](uint32_t stg, uint32_t coff) {
        const uint32_t sAh = stg, sAl = stg + A_TILE_B;
        const uint32_t sBh = stg + 2 * A_TILE_B, sBl = stg + 2 * A_TILE_B + B_TILE_B;
#pragma unroll
        for (int i = 0; i < 4; i++) {
            cpa16(sAh + ldA_dst[i], gAh + coff + ldA_src[i]);
            cpa16(sAl + ldA_dst[i], gAl + coff + ldA_src[i]);
        }
#pragma unroll
        for (int i = 0; i < 2; i++) {
            cpa16(sBh + ldB_dst[i], gBh + coff + ldB_src[i]);
            cpa16(sBl + ldB_dst[i], gBl + coff + ldB_src[i]);
        }
    };

    // prologue: stage 0 must be resident before first compute
    load_stage(sb, 0);
    CP_COMMIT();
    CP_WAIT0();
    __syncthreads();

    for (int c = 0; c < NCH; c++) {
        const int s = c & 1;
        const uint32_t stg = sb + (uint32_t)s * STAGE_B;
        const uint32_t sAh = stg, sAl = stg + A_TILE_B;
        const uint32_t sBh = stg + 2 * A_TILE_B, sBl = stg + 2 * A_TILE_B + B_TILE_B;

        auto compute_ks = [&](int ks) {
            const uint32_t kA = ((uint32_t)(ks * 32) + kselA) ^ swA;
            const uint32_t kB = ((uint32_t)(ks * 32) + kselB) ^ swB;

            uint32_t aH[2][4], aL[2][4];
            LDSM4(aH[0][0], aH[0][1], aH[0][2], aH[0][3], sAh + rowA + kA);
            LDSM4(aH[1][0], aH[1][1], aH[1][2], aH[1][3], sAh + rowA + 2048 + kA);
            LDSM4(aL[0][0], aL[0][1], aL[0][2], aL[0][3], sAl + rowA + kA);
            LDSM4(aL[1][0], aL[1][1], aL[1][2], aL[1][3], sAl + rowA + 2048 + kA);

#pragma unroll
            for (int np = 0; np < 2; np++) {
                uint32_t bh[4], bl[4];
                LDSM4(bh[0], bh[1], bh[2], bh[3], sBh + rowB[np] + kB);
                LDSM4(bl[0], bl[1], bl[2], bl[3], sBl + rowB[np] + kB);
#pragma unroll
                for (int half = 0; half < 2; half++) {
                    const int ns = np * 2 + half;
                    const uint32_t bh0 = bh[half * 2], bh1 = bh[half * 2 + 1];
                    const uint32_t bl0 = bl[half * 2], bl1 = bl[half * 2 + 1];
#pragma unroll
                    for (int ms = 0; ms < 2; ms++) {
                        mma16816(acc[ms][ns], aH[ms], bh0, bh1);
                        mma16816(acc[ms][ns], aH[ms], bl0, bl1);
                        mma16816(acc[ms][ns], aL[ms], bh0, bh1);
                    }
                }
            }
        };

        // ks0 first -> tensor pipe starts immediately after the barrier
        compute_ks(0);
        // then issue next chunk's loads (overlaps flight with ks1..3)
        if (c + 1 < NCH) {
            load_stage(sb + (uint32_t)(s ^ 1) * STAGE_B, (uint32_t)(c + 1) * KC * 2u);
            CP_COMMIT();
        }
        compute_ks(1);
        compute_ks(2);
        compute_ks(3);
        if (c + 1 < NCH) CP_WAIT0();
        __syncthreads();
    }

    // epilogue
#pragma unroll
    for (int ms = 0; ms < 2; ms++) {
        int row = bm + wm * 32 + ms * 16 + gid;
#pragma unroll
        for (int ns = 0; ns < 4; ns++) {
            int col = bn + wn * 32 + ns * 8 + tig * 2;
            float bx = __ldg(bias + col), by = __ldg(bias + col + 1);
            float2 v0 = make_float2(acc[ms][ns][0] + bx, acc[ms][ns][1] + by);
            float2 v1 = make_float2(acc[ms][ns][2] + bx, acc[ms][ns][3] + by);
            *reinterpret_cast<float2*>(C + (size_t)row * N + col) = v0;
            *reinterpret_cast<float2*>(C + (size_t)(row + 8) * N + col) = v1;
        }
    }
}

// ================= fused conversion kernel (one launch) =================
#define CONV_BLOCKS 11300

__global__ __launch_bounds__(256)
void conv_all_kernel(const float* __restrict__ input, const float* __restrict__ win,
                     const float* __restrict__ wout,
                     const float* __restrict__ woff, const float* __restrict__ boff,
                     const float* __restrict__ wmask, const float* __restrict__ bmask,
                     const float* __restrict__ wdw) {
    const int b = blockIdx.x;
    const int t = threadIdx.x;
    if (b < 10752) {
        const float* src; __nv_bfloat16 *hi, *lo; int i;
        if (b < 9216)       { src = input; hi = g_in_hi;  lo = g_in_lo;  i = b * 256 + t; }
        else if (b < 10240) { src = win;   hi = g_win_hi; lo = g_win_lo; i = (b - 9216) * 256 + t; }
        else                { src = wout;  hi = g_wout_hi; lo = g_wout_lo; i = (b - 10240) * 256 + t; }
        float4 v = reinterpret_cast<const float4*>(src)[i];
        __nv_bfloat16 h0, h1, h2, h3, l0, l1, l2, l3;
        split1(v.x, h0, l0); split1(v.y, h1, l1); split1(v.z, h2, l2); split1(v.w, h3, l3);
        __nv_bfloat162* hp = reinterpret_cast<__nv_bfloat162*>(hi) + i * 2;
        __nv_bfloat162* lp = reinterpret_cast<__nv_bfloat162*>(lo) + i * 2;
        hp[0] = __nv_bfloat162(h0, h1); hp[1] = __nv_bfloat162(h2, h3);
        lp[0] = __nv_bfloat162(l0, l1); lp[1] = __nv_bfloat162(l2, l3);
    } else if (b < 11264) {
        int i = (b - 10752) * 256 + t;
        int r = i >> 10, c = i & 1023;
        float v = 0.f;
        if (r < 72) v = woff[r * CC + c];
        else if (r < 108) v = wmask[(r - 72) * CC + c];
        __nv_bfloat16 h, l; split1(v, h, l);
        g_wom_hi[i] = h; g_wom_lo[i] = l;
        if (i < NFUSE) {
            float bb = 0.f;
            if (i < 72) bb = boff[i];
            else if (i < 108) bb = bmask[i - 72];
            g_bom[i] = bb;
        }
    } else {
        int i = (b - 11264) * 256 + t;
        int k = i >> 10, c = i & 1023;
        g_wdwt[k * CC + c] = wdw[c * 9 + k];
    }
}

// ================= depthwise conv 3x3 + LN + GELU -> split bf16 =================
__global__ __launch_bounds__(256)
void dw_ln_gelu_kernel(const float* __restrict__ in,
                       const float* __restrict__ bdw, const float* __restrict__ gamma,
                       const float* __restrict__ beta,
                       __nv_bfloat16* __restrict__ x1h, __nv_bfloat16* __restrict__ x1l) {
    const int pix = blockIdx.x;
    const int n = pix / (HH * WW);
    const int hw = pix % (HH * WW);
    const int h = hw / WW;
    const int w = hw % WW;
    const int t = threadIdx.x;
    const int c4 = t * 4;

    float4 acc = make_float4(0.f, 0.f, 0.f, 0.f);
#pragma unroll
    for (int kh = 0; kh < 3; kh++) {
        int y = h + kh - 1;
        if ((unsigned)y >= HH) continue;
#pragma unroll
        for (int kw = 0; kw < 3; kw++) {
            int x = w + kw - 1;
            if ((unsigned)x >= WW) continue;
            const float4 pv = *reinterpret_cast<const float4*>(
                in + (((size_t)n * HH + y) * WW + x) * CC + c4);
            const float4 wv = *reinterpret_cast<const float4*>(
                g_wdwt + (kh * 3 + kw) * CC + c4);
            acc.x = fmaf(pv.x, wv.x, acc.x);
            acc.y = fmaf(pv.y, wv.y, acc.y);
            acc.z = fmaf(pv.z, wv.z, acc.z);
            acc.w = fmaf(pv.w, wv.w, acc.w);
        }
    }
    const float4 bv = *reinterpret_cast<const float4*>(bdw + c4);
    float vals[4] = {acc.x + bv.x, acc.y + bv.y, acc.z + bv.z, acc.w + bv.w};
    float s = 0.f, s2 = 0.f;
#pragma unroll
    for (int i = 0; i < 4; i++) { s += vals[i]; s2 = fmaf(vals[i], vals[i], s2); }

    __shared__ float sh[16];
#pragma unroll
    for (int o = 16; o > 0; o >>= 1) {
        s  += __shfl_down_sync(0xFFFFFFFFu, s, o);
        s2 += __shfl_down_sync(0xFFFFFFFFu, s2, o);
    }
    int wd = t >> 5, ln = t & 31;
    if (ln == 0) { sh[wd] = s; sh[8 + wd] = s2; }
    __syncthreads();
    if (t == 0) {
        float S = 0.f, S2 = 0.f;
#pragma unroll
        for (int i = 0; i < 8; i++) { S += sh[i]; S2 += sh[8 + i]; }
        sh[0] = S; sh[8] = S2;
    }
    __syncthreads();
    float mean = sh[0] * (1.f / 1024.f);
    float var  = sh[8] * (1.f / 1024.f) - mean * mean;
    float rstd = rsqrtf(var + 1e-6f);

    const float4 gv = *reinterpret_cast<const float4*>(gamma + c4);
    const float4 btv = *reinterpret_cast<const float4*>(beta + c4);
    const float ga[4] = {gv.x, gv.y, gv.z, gv.w};
    const float be[4] = {btv.x, btv.y, btv.z, btv.w};

    __nv_bfloat16 hh[4], ll[4];
#pragma unroll
    for (int i = 0; i < 4; i++) {
        float y = (vals[i] - mean) * rstd * ga[i] + be[i];
        float g = 0.5f * y * (1.f + erff(y * 0.70710678118654752f));
        split1(g, hh[i], ll[i]);
    }
    const size_t ob = (size_t)pix * CC + c4;
    __nv_bfloat162* hp = reinterpret_cast<__nv_bfloat162*>(x1h + ob);
    __nv_bfloat162* lp = reinterpret_cast<__nv_bfloat162*>(x1l + ob);
    hp[0] = __nv_bfloat162(hh[0], hh[1]); hp[1] = __nv_bfloat162(hh[2], hh[3]);
    lp[0] = __nv_bfloat162(ll[0], ll[1]); lp[1] = __nv_bfloat162(ll[2], ll[3]);
}

// ================= DCNv3 core -> split bf16 (branchless gather, fp32 x) =================
__global__ __launch_bounds__(256)
void dcn_kernel(const float* __restrict__ x, const float* __restrict__ om,
                __nv_bfloat16* __restrict__ oh, __nv_bfloat16* __restrict__ ol) {
    const int pix = blockIdx.x;
    const int n = pix / (HH * WW);
    const int hw = pix % (HH * WW);
    const int h = hw / WW;
    const int w = hw % WW;
    const int t = threadIdx.x;
    const int g = t >> 6;
    const int ci = (t & 63) << 2;

    const float* row = om + (size_t)pix * NFUSE;
    const float* mrow = row + 72 + g * 9;
    const float* orow = row + g * 18;

    float ml[9], mx = -1e30f;
#pragma unroll
    for (int p = 0; p < 9; p++) { ml[p] = mrow[p]; mx = fmaxf(mx, ml[p]); }
    float se = 0.f;
#pragma unroll
    for (int p = 0; p < 9; p++) { ml[p] = expf(ml[p] - mx); se += ml[p]; }
    float inv = 1.f / se;

    const float* xg = x + g * GC + ci;
    const size_t nrow = (size_t)n * HH;
    float a0 = 0.f, a1 = 0.f, a2 = 0.f, a3 = 0.f;

#pragma unroll
    for (int p = 0; p < 9; p++) {
        float ox = orow[2 * p + 0];
        float oy = orow[2 * p + 1];
        float ux = (float)(w + (p / 3) - 1) + ox;
        float uy = (float)(h + (p % 3) - 1) + oy;
        float x0f = floorf(ux), y0f = floorf(uy);
        float fx = ux - x0f, fy = uy - y0f;
        int x0 = (int)x0f, y0 = (int)y0f;
        int x1i = x0 + 1, y1i = y0 + 1;

        float mx0 = ((unsigned)x0 < WW) ? 1.f : 0.f;
        float mx1 = ((unsigned)x1i < WW) ? 1.f : 0.f;
        float my0 = ((unsigned)y0 < HH) ? 1.f : 0.f;
        float my1 = ((unsigned)y1i < HH) ? 1.f : 0.f;
        int x0c = min(max(x0, 0), WW - 1), x1c = min(max(x1i, 0), WW - 1);
        int y0c = min(max(y0, 0), HH - 1), y1c = min(max(y1i, 0), HH - 1);

        const float* r0 = xg + ((nrow + y0c) * WW) * CC;
        const float* r1 = xg + ((nrow + y1c) * WW) * CC;
        float4 v00 = *reinterpret_cast<const float4*>(r0 + (size_t)x0c * CC);
        float4 v01 = *reinterpret_cast<const float4*>(r0 + (size_t)x1c * CC);
        float4 v10 = *reinterpret_cast<const float4*>(r1 + (size_t)x0c * CC);
        float4 v11 = *reinterpret_cast<const float4*>(r1 + (size_t)x1c * CC);

        const float wt = ml[p] * inv;
        const float w00 = (1.f - fx) * (1.f - fy) * my0 * mx0 * wt;
        const float w01 = fx * (1.f - fy) * my0 * mx1 * wt;
        const float w10 = (1.f - fx) * fy * my1 * mx0 * wt;
        const float w11 = fx * fy * my1 * mx1 * wt;

        a0 = fmaf(w00, v00.x, fmaf(w01, v01.x, fmaf(w10, v10.x, fmaf(w11, v11.x, a0))));
        a1 = fmaf(w00, v00.y, fmaf(w01, v01.y, fmaf(w10, v10.y, fmaf(w11, v11.y, a1))));
        a2 = fmaf(w00, v00.z, fmaf(w01, v01.z, fmaf(w10, v10.z, fmaf(w11, v11.z, a2))));
        a3 = fmaf(w00, v00.w, fmaf(w01, v01.w, fmaf(w10, v10.w, fmaf(w11, v11.w, a3))));
    }
    __nv_bfloat16 h0, h1, h2, h3, l0, l1, l2, l3;
    split1(a0, h0, l0); split1(a1, h1, l1); split1(a2, h2, l2); split1(a3, h3, l3);
    const size_t o = (size_t)pix * CC + g * GC + ci;
    __nv_bfloat162* hp = reinterpret_cast<__nv_bfloat162*>(oh + o);
    __nv_bfloat162* lp = reinterpret_cast<__nv_bfloat162*>(ol + o);
    hp[0] = __nv_bfloat162(h0, h1); hp[1] = __nv_bfloat162(h2, h3);
    lp[0] = __nv_bfloat162(l0, l1); lp[1] = __nv_bfloat162(l2, l3);
}

// ================= launch (capture-forked dual stream) =================
extern "C" void kernel_launch(void* const* d_in, const int* in_sizes, int n_in,
                              void* d_out, int out_size) {
    const float* input     = (const float*)d_in[0];
    const float* w_in_proj = (const float*)d_in[1];
    const float* b_in_proj = (const float*)d_in[2];
    const float* w_dw      = (const float*)d_in[3];
    const float* b_dw      = (const float*)d_in[4];
    const float* ln_gamma  = (const float*)d_in[5];
    const float* ln_beta   = (const float*)d_in[6];
    const float* w_offset  = (const float*)d_in[7];
    const float* b_offset  = (const float*)d_in[8];
    const float* w_mask    = (const float*)d_in[9];
    const float* b_mask    = (const float*)d_in[10];
    const float* w_out     = (const float*)d_in[11];
    const float* b_out     = (const float*)d_in[12];
    float* out = (float*)d_out;

    float *x, *om, *bom;
    __nv_bfloat16 *inh, *inl, *x1h, *x1l, *dch, *dcl;
    __nv_bfloat16 *winh, *winl, *wouth, *woutl, *womh, *woml;
    cudaGetSymbolAddress((void**)&x,    g_x);
    cudaGetSymbolAddress((void**)&om,   g_om);
    cudaGetSymbolAddress((void**)&bom,  g_bom);
    cudaGetSymbolAddress((void**)&inh,  g_in_hi);
    cudaGetSymbolAddress((void**)&inl,  g_in_lo);
    cudaGetSymbolAddress((void**)&x1h,  g_x1_hi);
    cudaGetSymbolAddress((void**)&x1l,  g_x1_lo);
    cudaGetSymbolAddress((void**)&dch,  g_dcn_hi);
    cudaGetSymbolAddress((void**)&dcl,  g_dcn_lo);
    cudaGetSymbolAddress((void**)&winh, g_win_hi);
    cudaGetSymbolAddress((void**)&winl, g_win_lo);
    cudaGetSymbolAddress((void**)&wouth, g_wout_hi);
    cudaGetSymbolAddress((void**)&woutl, g_wout_lo);
    cudaGetSymbolAddress((void**)&womh, g_wom_hi);
    cudaGetSymbolAddress((void**)&woml, g_wom_lo);

    cudaFuncSetAttribute(gemm_mma, cudaFuncAttributeMaxDynamicSharedMemorySize, GEMM_SMEM);

    cudaStream_t s1;
    cudaStreamCreateWithFlags(&s1, cudaStreamNonBlocking);
    cudaEvent_t eFork, eJoin;
    cudaEventCreateWithFlags(&eFork, cudaEventDisableTiming);
    cudaEventCreateWithFlags(&eJoin, cudaEventDisableTiming);

    // (1) all conversions in one launch (main stream)
    conv_all_kernel<<<CONV_BLOCKS, 256>>>(input, w_in_proj, w_out,
                                          w_offset, b_offset, w_mask, b_mask, w_dw);

    // fork: side chain does dw -> om gemm
    cudaEventRecord(eFork, 0);
    cudaStreamWaitEvent(s1, eFork, 0);

    // (2,3) side stream
    dw_ln_gelu_kernel<<<PIX, 256, 0, s1>>>(input, b_dw, ln_gamma, ln_beta, x1h, x1l);
    gemm_mma<<<dim3(NFUSE / 64, PIX / 128), 256, GEMM_SMEM, s1>>>(x1h, x1l, womh, woml,
                                                                  bom, om, NFUSE, CC);

    // (4) main stream: in_proj
    gemm_mma<<<dim3(CC / 64, PIX / 128), 256, GEMM_SMEM>>>(inh, inl, winh, winl,
                                                           b_in_proj, x, CC, CC);

    // join
    cudaEventRecord(eJoin, s1);
    cudaStreamWaitEvent(0, eJoin, 0);

    // (5) dcn, (6) out projection
    dcn_kernel<<<PIX, 256>>>(x, om, dch, dcl);
    gemm_mma<<<dim3(COUT / 64, PIX / 128), 256, GEMM_SMEM>>>(dch, dcl, wouth, woutl,
                                                             b_out, out, COUT, CC);
}